// round 6
// baseline (speedup 1.0000x reference)
#include <cuda_runtime.h>
#include <math.h>

#define Nn 30000
#define Ee 960000
#define ET (Ee + Nn)
#define Hh 2
#define Cc 128
#define HC 256
#define Gg 64
#define EPSB 1e-5f

typedef unsigned long long ull;

// ---------------- scratch (device globals; no allocation allowed) ----------------
__device__ float  g_xp[(size_t)Nn * HC];     // x @ gat_w          [N,256]
__device__ float  g_as[Nn * Hh];             // attention src dots [N,2]
__device__ float  g_ad[Nn * Hh];             // attention dst dots [N,2]
__device__ int    g_deg[Nn];                 // in-degree
__device__ int    g_ptr[Nn + 1];             // CSR offsets
__device__ int    g_cur[Nn];                 // scatter cursors
__device__ int4   g_csre[ET];                // CSR edge: {src, w0, w1, pad}
__device__ float  g_acc[(size_t)Nn * HC];    // normalized aggregation
__device__ float  g_h1[(size_t)Nn * Cc];     // elu(out) @ mlp_w + b
__device__ float  g_bnsum[2 * Cc];
__device__ float  g_sc0[Cc], g_sh0[Cc];
__device__ float  g_hp[Gg * Cc];
__device__ float  g_z1[Gg * 512];
__device__ float  g_sc1[512], g_sh1[512];
__device__ float  g_z2[Gg * 256];
__device__ float  g_sc2[256], g_sh2[256];

// ---------------- f32x2 helpers ----------------
__device__ __forceinline__ ull pk2(float lo, float hi) {
    ull d;
    asm("mov.b64 %0, {%1, %2};" : "=l"(d) : "r"(__float_as_uint(lo)), "r"(__float_as_uint(hi)));
    return d;
}
__device__ __forceinline__ float2 upk(ull v) {
    unsigned lo, hi;
    asm("mov.b64 {%0, %1}, %2;" : "=r"(lo), "=r"(hi) : "l"(v));
    return make_float2(__uint_as_float(lo), __uint_as_float(hi));
}
__device__ __forceinline__ ull fma2(ull a, ull b, ull c) {
    ull d;
    asm("fma.rn.f32x2 %0, %1, %2, %3;" : "=l"(d) : "l"(a), "l"(b), "l"(c));
    return d;
}

// ---------------- init ----------------
__global__ void k_init() {
    int i = blockIdx.x * blockDim.x + threadIdx.x;
    if (i < Nn)      g_deg[i] = 0;
    if (i < Gg * Cc) g_hp[i] = 0.f;
    if (i < 2 * Cc)  g_bnsum[i] = 0.f;
}

// ---------------- f32x2 GEMM: 128x128x16, 512 thr, 4x8/thread, double-buffered ----
// MODE 0: C(g_xp) = Aext @ B;  epilogue also writes attention dots g_as/g_ad
// MODE 1: C(g_h1) = elu(g_acc + abias) @ B + cbias
template <int MODE>
__global__ void __launch_bounds__(512, 2)
k_gemm(const float* __restrict__ Aext, const float* __restrict__ B,
       const float* __restrict__ cbias, const float* __restrict__ abias,
       const float* __restrict__ asrc, const float* __restrict__ adst,
       int M, int K, int Nc) {
    __shared__ float As[2][16][128];
    __shared__ float Bs[2][16][128];
    int t = threadIdx.x;
    int tx = t & 15, ty = t >> 4;                 // ty: 0..31 (4 M-rows each)
    int m0 = blockIdx.x * 128, n0 = blockIdx.y * 128;

    int arow = t >> 2, ak4 = (t & 3) << 2;        // A stage: 1 float4 / thread
    int brow = t >> 5, bc4 = (t & 31) << 2;       // B stage: 1 float4 / thread
    int steps = K >> 4;
    bool rowok = (m0 + arow) < M;
    const float* Ab = ((MODE == 0) ? Aext : (const float*)g_acc) + (size_t)(m0 + arow) * K + ak4;
    const float* Bb = B + (size_t)brow * Nc + n0 + bc4;

    ull acc[2][8];
#pragma unroll
    for (int i = 0; i < 2; i++)
#pragma unroll
        for (int j = 0; j < 8; j++) acc[i][j] = 0ull;

    float4 av, bv;
    auto load = [&](int s, float4& va, float4& vb) {
        int k0 = s << 4;
        va = make_float4(0.f, 0.f, 0.f, 0.f);
        if (rowok) {
            va = *(const float4*)(Ab + k0);
            if (MODE == 1) {
                int gk = k0 + ak4;
                float f[4] = {va.x, va.y, va.z, va.w};
#pragma unroll
                for (int j = 0; j < 4; j++) {
                    float u = f[j] + __ldg(abias + gk + j);
                    f[j] = u > 0.f ? u : (__expf(u) - 1.f);
                }
                va = make_float4(f[0], f[1], f[2], f[3]);
            }
        }
        vb = *(const float4*)(Bb + (size_t)k0 * Nc);
    };
    auto stash = [&](int buf, const float4& va, const float4& vb) {
        As[buf][ak4 + 0][arow] = va.x;
        As[buf][ak4 + 1][arow] = va.y;
        As[buf][ak4 + 2][arow] = va.z;
        As[buf][ak4 + 3][arow] = va.w;
        *(float4*)&Bs[buf][brow][bc4] = vb;
    };

    load(0, av, bv);
    stash(0, av, bv);
    __syncthreads();

    for (int it = 0; it < steps; it++) {
        int buf = it & 1;
        if (it + 1 < steps) load(it + 1, av, bv);
#pragma unroll
        for (int k = 0; k < 16; k++) {
            float4 x = *(const float4*)&As[buf][k][ty * 4];
            float4 y0 = *(const float4*)&Bs[buf][k][tx * 8];
            float4 y1 = *(const float4*)&Bs[buf][k][tx * 8 + 4];
            ull A01 = pk2(x.x, x.y), A23 = pk2(x.z, x.w);
            float bb[8] = {y0.x, y0.y, y0.z, y0.w, y1.x, y1.y, y1.z, y1.w};
#pragma unroll
            for (int j = 0; j < 8; j++) {
                ull B2 = pk2(bb[j], bb[j]);
                acc[0][j] = fma2(A01, B2, acc[0][j]);
                acc[1][j] = fma2(A23, B2, acc[1][j]);
            }
        }
        if (it + 1 < steps) stash((it + 1) & 1, av, bv);
        __syncthreads();
    }

    float* Cp = (MODE == 0) ? g_xp : g_h1;
    float cb[8];
#pragma unroll
    for (int j = 0; j < 8; j++) cb[j] = cbias ? cbias[n0 + tx * 8 + j] : 0.f;

    float sa[8], da[8];
    int h = n0 >> 7;
    if (MODE == 0) {
#pragma unroll
        for (int j = 0; j < 8; j++) {
            sa[j] = asrc[(h << 7) + tx * 8 + j];
            da[j] = adst[(h << 7) + tx * 8 + j];
        }
    }

#pragma unroll
    for (int i = 0; i < 2; i++) {
        float2 p[8];
#pragma unroll
        for (int j = 0; j < 8; j++) p[j] = upk(acc[i][j]);
        int re = m0 + ty * 4 + i * 2;
        int gc = n0 + tx * 8;
        if (re < M) {
            *(float4*)(Cp + (size_t)re * Nc + gc) =
                make_float4(p[0].x + cb[0], p[1].x + cb[1], p[2].x + cb[2], p[3].x + cb[3]);
            *(float4*)(Cp + (size_t)re * Nc + gc + 4) =
                make_float4(p[4].x + cb[4], p[5].x + cb[5], p[6].x + cb[6], p[7].x + cb[7]);
        }
        if (re + 1 < M) {
            *(float4*)(Cp + (size_t)(re + 1) * Nc + gc) =
                make_float4(p[0].y + cb[0], p[1].y + cb[1], p[2].y + cb[2], p[3].y + cb[3]);
            *(float4*)(Cp + (size_t)(re + 1) * Nc + gc + 4) =
                make_float4(p[4].y + cb[4], p[5].y + cb[5], p[6].y + cb[6], p[7].y + cb[7]);
        }
        if (MODE == 0) {
            float s0 = 0.f, d0 = 0.f, s1 = 0.f, d1 = 0.f;
#pragma unroll
            for (int j = 0; j < 8; j++) {
                s0 += p[j].x * sa[j]; d0 += p[j].x * da[j];
                s1 += p[j].y * sa[j]; d1 += p[j].y * da[j];
            }
#pragma unroll
            for (int msk = 1; msk < 16; msk <<= 1) {
                s0 += __shfl_xor_sync(0xFFFFFFFFu, s0, msk);
                d0 += __shfl_xor_sync(0xFFFFFFFFu, d0, msk);
                s1 += __shfl_xor_sync(0xFFFFFFFFu, s1, msk);
                d1 += __shfl_xor_sync(0xFFFFFFFFu, d1, msk);
            }
            if (tx == 0) {
                if (re < M)     { g_as[re * 2 + h] = s0;       g_ad[re * 2 + h] = d0; }
                if (re + 1 < M) { g_as[(re + 1) * 2 + h] = s1; g_ad[(re + 1) * 2 + h] = d1; }
            }
        }
    }
}

// ---------------- degree count ----------------
__global__ void k_degree(const int* __restrict__ ei) {
    int i = blockIdx.x * blockDim.x + threadIdx.x;
    if (i >= ET) return;
    int dst = (i < Ee) ? ei[Ee + i] : (i - Ee);
    atomicAdd(&g_deg[dst], 1);
}

// ---------------- exclusive scan (single block) ----------------
__global__ void k_scan() {
    __shared__ int sh[1024];
    int t = threadIdx.x;
    int s = t * 30, e = min(Nn, s + 30);
    int sum = 0;
    for (int i = s; i < e; i++) sum += g_deg[i];
    sh[t] = sum;
    __syncthreads();
    for (int off = 1; off < 1024; off <<= 1) {
        int v = (t >= off) ? sh[t - off] : 0;
        __syncthreads();
        sh[t] += v;
        __syncthreads();
    }
    int run = t ? sh[t - 1] : 0;
    for (int i = s; i < e; i++) {
        g_ptr[i] = run;
        g_cur[i] = run;
        run += g_deg[i];
    }
    if (t == 1023) g_ptr[Nn] = sh[1023];
}

// ---------------- fused edge: logit -> exp -> CSR scatter (packed 16B) ----------
__global__ void k_edge(const int* __restrict__ ei) {
    int i = blockIdx.x * blockDim.x + threadIdx.x;
    if (i >= ET) return;
    int src, dst;
    if (i < Ee) { src = ei[i]; dst = ei[Ee + i]; }
    else        { src = dst = i - Ee; }
    float2 as = *(const float2*)(g_as + src * 2);
    float2 ad = *(const float2*)(g_ad + dst * 2);
    float l0 = as.x + ad.x; l0 = l0 > 0.f ? l0 : 0.2f * l0;
    float l1 = as.y + ad.y; l1 = l1 > 0.f ? l1 : 0.2f * l1;
    float w0 = __expf(l0), w1 = __expf(l1);
    int pos = atomicAdd(&g_cur[dst], 1);
    g_csre[pos] = make_int4(src, __float_as_int(w0), __float_as_int(w1), 0);
}

// ---------------- aggregation: block per dst, 4 edge-groups x 64 thr, float4 ------
__global__ void __launch_bounds__(256) k_agg() {
    __shared__ float4 sha[256];
    __shared__ float  shw[256];
    int dst = blockIdx.x;
    int t = threadIdx.x;
    int grp = t >> 6, l = t & 63;
    int beg = g_ptr[dst], end = g_ptr[dst + 1];
    bool hi = l >= 32;
    float4 acc = make_float4(0.f, 0.f, 0.f, 0.f);
    float wsum = 0.f;
#pragma unroll 2
    for (int e = beg + grp; e < end; e += 4) {
        int4 ew = __ldg(&g_csre[e]);
        float ww = hi ? __int_as_float(ew.z) : __int_as_float(ew.y);
        float4 v = __ldg((const float4*)(g_xp + (size_t)ew.x * HC) + l);
        acc.x += v.x * ww; acc.y += v.y * ww;
        acc.z += v.z * ww; acc.w += v.w * ww;
        wsum += ww;
    }
    sha[t] = acc; shw[t] = wsum;
    __syncthreads();
    if (grp == 0) {
        float4 a = sha[t], b = sha[t + 64], c = sha[t + 128], d = sha[t + 192];
        float rd = 1.f / (shw[t] + shw[t + 64] + shw[t + 128] + shw[t + 192]);
        float4 r = make_float4((a.x + b.x + c.x + d.x) * rd,
                               (a.y + b.y + c.y + d.y) * rd,
                               (a.z + b.z + c.z + d.z) * rd,
                               (a.w + b.w + c.w + d.w) * rd);
        *((float4*)(g_acc + (size_t)dst * HC) + l) = r;
    }
}

// ---------------- BN0 stats ----------------
__global__ void k_bn0_stats() {
    int c = threadIdx.x;  // 128
    float s = 0.f, s2 = 0.f;
    for (int n = blockIdx.x; n < Nn; n += gridDim.x) {
        float v = g_h1[(size_t)n * Cc + c];
        s += v; s2 += v * v;
    }
    atomicAdd(&g_bnsum[c], s);
    atomicAdd(&g_bnsum[Cc + c], s2);
}

__global__ void k_bn0_final(const float* __restrict__ g, const float* __restrict__ b) {
    int c = threadIdx.x;
    if (c < Cc) {
        float mean = g_bnsum[c] / (float)Nn;
        float var  = fmaxf(g_bnsum[Cc + c] / (float)Nn - mean * mean, 0.f);
        float sc = g[c] * rsqrtf(var + EPSB);
        g_sc0[c] = sc;
        g_sh0[c] = b[c] - mean * sc;
    }
}

// ---------------- normalize + pool ----------------
__global__ void k_pool(const int* __restrict__ batch) {
    int c = threadIdx.x;  // 128
    int per = (Nn + gridDim.x - 1) / gridDim.x;
    int s = blockIdx.x * per;
    int e = min(Nn, s + per);
    if (s >= e) return;
    float sc = g_sc0[c], sh = g_sh0[c];
    int cur = batch[s];
    float a = 0.f;
    for (int n = s; n < e; n++) {
        int gi = batch[n];
        if (gi != cur) { atomicAdd(&g_hp[cur * Cc + c], a); a = 0.f; cur = gi; }
        a += g_h1[(size_t)n * Cc + c] * sc + sh;
    }
    atomicAdd(&g_hp[cur * Cc + c], a);
}

// ---------------- FC stack ----------------
__global__ void k_fc1(const float* __restrict__ w, const float* __restrict__ b) {
    int idx = blockIdx.x * blockDim.x + threadIdx.x;
    if (idx >= Gg * 512) return;
    int c = idx & 511, r = idx >> 9;
    float s = b[c];
#pragma unroll 8
    for (int k = 0; k < Cc; k++) s += g_hp[r * Cc + k] * w[k * 512 + c];
    g_z1[idx] = s;
}

__global__ void k_bn1(const float* __restrict__ g, const float* __restrict__ b) {
    int c = blockIdx.x * blockDim.x + threadIdx.x;
    if (c >= 512) return;
    float s = 0.f, s2 = 0.f;
    for (int r = 0; r < Gg; r++) { float v = g_z1[r * 512 + c]; s += v; s2 += v * v; }
    float mean = s / (float)Gg;
    float var = fmaxf(s2 / (float)Gg - mean * mean, 0.f);
    float sc = g[c] * rsqrtf(var + EPSB);
    g_sc1[c] = sc; g_sh1[c] = b[c] - mean * sc;
}

__global__ void k_fc2(const float* __restrict__ w, const float* __restrict__ b) {
    int idx = blockIdx.x * blockDim.x + threadIdx.x;
    if (idx >= Gg * 256) return;
    int c = idx & 255, r = idx >> 8;
    float s = b[c];
#pragma unroll 8
    for (int k = 0; k < 512; k++) {
        float v = fmaxf(g_z1[r * 512 + k] * g_sc1[k] + g_sh1[k], 0.f);
        s += v * w[k * 256 + c];
    }
    g_z2[idx] = s;
}

__global__ void k_bn2(const float* __restrict__ g, const float* __restrict__ b) {
    int c = threadIdx.x;
    if (c >= 256) return;
    float s = 0.f, s2 = 0.f;
    for (int r = 0; r < Gg; r++) { float v = g_z2[r * 256 + c]; s += v; s2 += v * v; }
    float mean = s / (float)Gg;
    float var = fmaxf(s2 / (float)Gg - mean * mean, 0.f);
    float sc = g[c] * rsqrtf(var + EPSB);
    g_sc2[c] = sc; g_sh2[c] = b[c] - mean * sc;
}

__global__ void k_fc3(const float* __restrict__ w, const float* __restrict__ b,
                      const float* __restrict__ g3, const float* __restrict__ b3,
                      float* __restrict__ out) {
    __shared__ float red[256];
    __shared__ float z3[64];
    __shared__ float mv[2];
    int t = threadIdx.x;
    int r = t >> 2, p = t & 3;
    float s = 0.f;
    for (int k = p * 64; k < p * 64 + 64; k++) {
        float v = fmaxf(g_z2[r * 256 + k] * g_sc2[k] + g_sh2[k], 0.f);
        s += v * w[k];
    }
    red[t] = s;
    __syncthreads();
    if (p == 0) z3[r] = red[t] + red[t + 1] + red[t + 2] + red[t + 3] + b[0];
    __syncthreads();
    if (t == 0) {
        float m = 0.f;
        for (int i = 0; i < 64; i++) m += z3[i];
        m /= 64.f;
        float v = 0.f;
        for (int i = 0; i < 64; i++) { float d = z3[i] - m; v += d * d; }
        v /= 64.f;
        mv[0] = m; mv[1] = rsqrtf(v + EPSB);
    }
    __syncthreads();
    if (t < 64) out[t] = (z3[t] - mv[0]) * mv[1] * g3[0] + b3[0];
}

// ---------------- launch ----------------
extern "C" void kernel_launch(void* const* d_in, const int* in_sizes, int n_in,
                              void* d_out, int out_size) {
    const float* x        = (const float*)d_in[0];
    const float* gat_w    = (const float*)d_in[1];
    const float* gat_asrc = (const float*)d_in[2];
    const float* gat_adst = (const float*)d_in[3];
    const float* gat_bias = (const float*)d_in[4];
    const float* mlp_w    = (const float*)d_in[5];
    const float* mlp_b    = (const float*)d_in[6];
    const float* bn0_g    = (const float*)d_in[7];
    const float* bn0_b    = (const float*)d_in[8];
    const float* fc1_w    = (const float*)d_in[9];
    const float* fc1_b    = (const float*)d_in[10];
    const float* bn1_g    = (const float*)d_in[11];
    const float* bn1_b    = (const float*)d_in[12];
    const float* fc2_w    = (const float*)d_in[13];
    const float* fc2_b    = (const float*)d_in[14];
    const float* bn2_g    = (const float*)d_in[15];
    const float* bn2_b    = (const float*)d_in[16];
    const float* fc3_w    = (const float*)d_in[17];
    const float* fc3_b    = (const float*)d_in[18];
    const float* bn3_g    = (const float*)d_in[19];
    const float* bn3_b    = (const float*)d_in[20];
    const int*   ei       = (const int*)d_in[21];
    const int*   batch    = (const int*)d_in[22];
    float* out = (float*)d_out;

    // order chosen so gemm0 is the 4th launch (ncu lands there)
    k_init<<<(Nn + 255) / 256, 256>>>();
    k_degree<<<(ET + 255) / 256, 256>>>(ei);
    k_scan<<<1, 1024>>>();
    k_gemm<0><<<dim3((Nn + 127) / 128, HC / 128), 512>>>(
        x, gat_w, nullptr, nullptr, gat_asrc, gat_adst, Nn, 448, HC);
    k_edge<<<(ET + 255) / 256, 256>>>(ei);
    k_agg<<<Nn, 256>>>();
    k_gemm<1><<<dim3((Nn + 127) / 128, Cc / 128), 512>>>(
        nullptr, mlp_w, mlp_b, gat_bias, nullptr, nullptr, Nn, HC, Cc);
    k_bn0_stats<<<512, 128>>>();
    k_bn0_final<<<1, 128>>>(bn0_g, bn0_b);
    k_pool<<<200, 128>>>(batch);
    k_fc1<<<(Gg * 512 + 255) / 256, 256>>>(fc1_w, fc1_b);
    k_bn1<<<2, 256>>>(bn1_g, bn1_b);
    k_fc2<<<(Gg * 256 + 255) / 256, 256>>>(fc2_w, fc2_b);
    k_bn2<<<1, 256>>>(bn2_g, bn2_b);
    k_fc3<<<1, 256>>>(fc3_w, fc3_b, bn3_g, bn3_b, out);
}

// round 7
// speedup vs baseline: 1.2486x; 1.2486x over previous
#include <cuda_runtime.h>
#include <math.h>

#define Nn 30000
#define Ee 960000
#define ET (Ee + Nn)
#define Hh 2
#define Cc 128
#define HC 256
#define Gg 64
#define EPSB 1e-5f

typedef unsigned long long ull;

// ---------------- scratch (device globals; no allocation allowed) ----------------
__device__ float  g_xp[(size_t)Nn * HC];     // x @ gat_w          [N,256]
__device__ float  g_as[Nn * Hh];             // attention src dots [N,2]
__device__ float  g_ad[Nn * Hh];             // attention dst dots [N,2]
__device__ int    g_deg[Nn];                 // in-degree
__device__ int    g_ptr[Nn + 1];             // CSR offsets
__device__ int    g_cur[Nn];                 // scatter cursors
__device__ int4   g_csre[ET];                // CSR edge: {src, w0, w1, pad}
__device__ float  g_acc[(size_t)Nn * HC];    // normalized aggregation
__device__ float  g_h1[(size_t)Nn * Cc];     // elu(out) @ mlp_w + b
__device__ float  g_bnsum[2 * Cc];
__device__ float  g_sc0[Cc], g_sh0[Cc];
__device__ float  g_hp[Gg * Cc];
__device__ float  g_z1[Gg * 512];
__device__ float  g_sc1[512], g_sh1[512];
__device__ float  g_z2[Gg * 256];
__device__ float  g_sc2[256], g_sh2[256];

// ---------------- f32x2 helpers ----------------
__device__ __forceinline__ ull pk2(float lo, float hi) {
    ull d;
    asm("mov.b64 %0, {%1, %2};" : "=l"(d) : "r"(__float_as_uint(lo)), "r"(__float_as_uint(hi)));
    return d;
}
__device__ __forceinline__ float2 upk(ull v) {
    unsigned lo, hi;
    asm("mov.b64 {%0, %1}, %2;" : "=r"(lo), "=r"(hi) : "l"(v));
    return make_float2(__uint_as_float(lo), __uint_as_float(hi));
}
__device__ __forceinline__ ull fma2(ull a, ull b, ull c) {
    ull d;
    asm("fma.rn.f32x2 %0, %1, %2, %3;" : "=l"(d) : "l"(a), "l"(b), "l"(c));
    return d;
}

// ---------------- init ----------------
__global__ void k_init() {
    int i = blockIdx.x * blockDim.x + threadIdx.x;
    if (i < Nn)      g_deg[i] = 0;
    if (i < Gg * Cc) g_hp[i] = 0.f;
    if (i < 2 * Cc)  g_bnsum[i] = 0.f;
}

// ---------------- f32x2 GEMM: 128x128x16, 256 thr, 8x8/thread, 2 CTAs/SM --------
// Single-buffered smem (16KB) so 2 CTAs/SM fit; inter-CTA overlap hides the
// load/sync bubble that the old double-buffer handled.
// MODE 0: C(g_xp) = Aext @ B;  epilogue also writes attention dots g_as/g_ad
// MODE 1: C(g_h1) = elu(g_acc + abias) @ B + cbias
template <int MODE>
__global__ void __launch_bounds__(256, 2)
k_gemm(const float* __restrict__ Aext, const float* __restrict__ B,
       const float* __restrict__ cbias, const float* __restrict__ abias,
       const float* __restrict__ asrc, const float* __restrict__ adst,
       int M, int K, int Nc) {
    __shared__ float As[16][128];
    __shared__ float Bs[16][128];
    int t = threadIdx.x;
    int tx = t & 15, ty = t >> 4;
    int m0 = blockIdx.x * 128, n0 = blockIdx.y * 128;
    int ar_ = t >> 1, akc = (t & 1) * 8;
    int bkb = t >> 4, bc4 = (t & 15) * 8;
    int steps = K >> 4;
    bool rowok = (m0 + ar_) < M;
    const float* Ab = ((MODE == 0) ? Aext : (const float*)g_acc) + (size_t)(m0 + ar_) * K + akc;
    const float* Bb = B + (size_t)bkb * Nc + n0 + bc4;

    ull acc[4][8];
#pragma unroll
    for (int i = 0; i < 4; i++)
#pragma unroll
        for (int j = 0; j < 8; j++) acc[i][j] = 0ull;

    for (int it = 0; it < steps; it++) {
        int k0 = it << 4;
        float4 va0 = make_float4(0.f, 0.f, 0.f, 0.f), va1 = va0;
        if (rowok) {
            va0 = *(const float4*)(Ab + k0);
            va1 = *(const float4*)(Ab + k0 + 4);
            if (MODE == 1) {
                int gk = k0 + akc;
                float f[8] = {va0.x, va0.y, va0.z, va0.w, va1.x, va1.y, va1.z, va1.w};
#pragma unroll
                for (int j = 0; j < 8; j++) {
                    float u = f[j] + __ldg(abias + gk + j);
                    f[j] = u > 0.f ? u : (__expf(u) - 1.f);
                }
                va0 = make_float4(f[0], f[1], f[2], f[3]);
                va1 = make_float4(f[4], f[5], f[6], f[7]);
            }
        }
        float4 vb0 = *(const float4*)(Bb + (size_t)k0 * Nc);
        float4 vb1 = *(const float4*)(Bb + (size_t)k0 * Nc + 4);

        __syncthreads();   // previous compute done before overwrite
        As[akc + 0][ar_] = va0.x; As[akc + 1][ar_] = va0.y;
        As[akc + 2][ar_] = va0.z; As[akc + 3][ar_] = va0.w;
        As[akc + 4][ar_] = va1.x; As[akc + 5][ar_] = va1.y;
        As[akc + 6][ar_] = va1.z; As[akc + 7][ar_] = va1.w;
        *(float4*)&Bs[bkb][bc4]     = vb0;
        *(float4*)&Bs[bkb][bc4 + 4] = vb1;
        __syncthreads();

#pragma unroll
        for (int k = 0; k < 16; k++) {
            float4 x0 = *(const float4*)&As[k][ty * 8];
            float4 x1 = *(const float4*)&As[k][ty * 8 + 4];
            float4 y0 = *(const float4*)&Bs[k][tx * 8];
            float4 y1 = *(const float4*)&Bs[k][tx * 8 + 4];
            ull A2[4] = {pk2(x0.x, x0.y), pk2(x0.z, x0.w),
                         pk2(x1.x, x1.y), pk2(x1.z, x1.w)};
            float bb[8] = {y0.x, y0.y, y0.z, y0.w, y1.x, y1.y, y1.z, y1.w};
#pragma unroll
            for (int j = 0; j < 8; j++) {
                ull B2 = pk2(bb[j], bb[j]);
#pragma unroll
                for (int i = 0; i < 4; i++) acc[i][j] = fma2(A2[i], B2, acc[i][j]);
            }
        }
    }

    float* Cp = (MODE == 0) ? g_xp : g_h1;
    float cb[8];
#pragma unroll
    for (int j = 0; j < 8; j++) cb[j] = cbias ? cbias[n0 + tx * 8 + j] : 0.f;

    float sa[8], da[8];
    int h = n0 >> 7;
    if (MODE == 0) {
#pragma unroll
        for (int j = 0; j < 8; j++) {
            sa[j] = asrc[(h << 7) + tx * 8 + j];
            da[j] = adst[(h << 7) + tx * 8 + j];
        }
    }

#pragma unroll
    for (int i = 0; i < 4; i++) {
        float2 p[8];
#pragma unroll
        for (int j = 0; j < 8; j++) p[j] = upk(acc[i][j]);
        int re = m0 + ty * 8 + i * 2;
        int gc = n0 + tx * 8;
        if (re < M) {
            *(float4*)(Cp + (size_t)re * Nc + gc) =
                make_float4(p[0].x + cb[0], p[1].x + cb[1], p[2].x + cb[2], p[3].x + cb[3]);
            *(float4*)(Cp + (size_t)re * Nc + gc + 4) =
                make_float4(p[4].x + cb[4], p[5].x + cb[5], p[6].x + cb[6], p[7].x + cb[7]);
        }
        if (re + 1 < M) {
            *(float4*)(Cp + (size_t)(re + 1) * Nc + gc) =
                make_float4(p[0].y + cb[0], p[1].y + cb[1], p[2].y + cb[2], p[3].y + cb[3]);
            *(float4*)(Cp + (size_t)(re + 1) * Nc + gc + 4) =
                make_float4(p[4].y + cb[4], p[5].y + cb[5], p[6].y + cb[6], p[7].y + cb[7]);
        }
        if (MODE == 0) {
            float s0 = 0.f, d0 = 0.f, s1 = 0.f, d1 = 0.f;
#pragma unroll
            for (int j = 0; j < 8; j++) {
                s0 += p[j].x * sa[j]; d0 += p[j].x * da[j];
                s1 += p[j].y * sa[j]; d1 += p[j].y * da[j];
            }
#pragma unroll
            for (int msk = 1; msk < 16; msk <<= 1) {
                s0 += __shfl_xor_sync(0xFFFFFFFFu, s0, msk);
                d0 += __shfl_xor_sync(0xFFFFFFFFu, d0, msk);
                s1 += __shfl_xor_sync(0xFFFFFFFFu, s1, msk);
                d1 += __shfl_xor_sync(0xFFFFFFFFu, d1, msk);
            }
            if (tx == 0) {
                if (re < M)     { g_as[re * 2 + h] = s0;       g_ad[re * 2 + h] = d0; }
                if (re + 1 < M) { g_as[(re + 1) * 2 + h] = s1; g_ad[(re + 1) * 2 + h] = d1; }
            }
        }
    }
}

// ---------------- degree count ----------------
__global__ void k_degree(const int* __restrict__ ei) {
    int i = blockIdx.x * blockDim.x + threadIdx.x;
    if (i >= ET) return;
    int dst = (i < Ee) ? ei[Ee + i] : (i - Ee);
    atomicAdd(&g_deg[dst], 1);
}

// ---------------- exclusive scan (single block) ----------------
__global__ void k_scan() {
    __shared__ int sh[1024];
    int t = threadIdx.x;
    int s = t * 30, e = min(Nn, s + 30);
    int sum = 0;
    for (int i = s; i < e; i++) sum += g_deg[i];
    sh[t] = sum;
    __syncthreads();
    for (int off = 1; off < 1024; off <<= 1) {
        int v = (t >= off) ? sh[t - off] : 0;
        __syncthreads();
        sh[t] += v;
        __syncthreads();
    }
    int run = t ? sh[t - 1] : 0;
    for (int i = s; i < e; i++) {
        g_ptr[i] = run;
        g_cur[i] = run;
        run += g_deg[i];
    }
    if (t == 1023) g_ptr[Nn] = sh[1023];
}

// ---------------- fused edge: logit -> exp -> CSR scatter (packed 16B) ----------
__global__ void k_edge(const int* __restrict__ ei) {
    int i = blockIdx.x * blockDim.x + threadIdx.x;
    if (i >= ET) return;
    int src, dst;
    if (i < Ee) { src = ei[i]; dst = ei[Ee + i]; }
    else        { src = dst = i - Ee; }
    float2 as = *(const float2*)(g_as + src * 2);
    float2 ad = *(const float2*)(g_ad + dst * 2);
    float l0 = as.x + ad.x; l0 = l0 > 0.f ? l0 : 0.2f * l0;
    float l1 = as.y + ad.y; l1 = l1 > 0.f ? l1 : 0.2f * l1;
    float w0 = __expf(l0), w1 = __expf(l1);
    int pos = atomicAdd(&g_cur[dst], 1);
    g_csre[pos] = make_int4(src, __float_as_int(w0), __float_as_int(w1), 0);
}

// ---------------- aggregation: block per dst, 4 edge-groups x 64 thr, float4 ------
__global__ void __launch_bounds__(256) k_agg() {
    __shared__ float4 sha[256];
    __shared__ float  shw[256];
    int dst = blockIdx.x;
    int t = threadIdx.x;
    int grp = t >> 6, l = t & 63;
    int beg = g_ptr[dst], end = g_ptr[dst + 1];
    bool hi = l >= 32;
    float4 acc = make_float4(0.f, 0.f, 0.f, 0.f);
    float wsum = 0.f;
#pragma unroll 2
    for (int e = beg + grp; e < end; e += 4) {
        int4 ew = __ldg(&g_csre[e]);
        float ww = hi ? __int_as_float(ew.z) : __int_as_float(ew.y);
        float4 v = __ldg((const float4*)(g_xp + (size_t)ew.x * HC) + l);
        acc.x += v.x * ww; acc.y += v.y * ww;
        acc.z += v.z * ww; acc.w += v.w * ww;
        wsum += ww;
    }
    sha[t] = acc; shw[t] = wsum;
    __syncthreads();
    if (grp == 0) {
        float4 a = sha[t], b = sha[t + 64], c = sha[t + 128], d = sha[t + 192];
        float rd = 1.f / (shw[t] + shw[t + 64] + shw[t + 128] + shw[t + 192]);
        float4 r = make_float4((a.x + b.x + c.x + d.x) * rd,
                               (a.y + b.y + c.y + d.y) * rd,
                               (a.z + b.z + c.z + d.z) * rd,
                               (a.w + b.w + c.w + d.w) * rd);
        *((float4*)(g_acc + (size_t)dst * HC) + l) = r;
    }
}

// ---------------- BN0 stats ----------------
__global__ void k_bn0_stats() {
    int c = threadIdx.x;  // 128
    float s = 0.f, s2 = 0.f;
    for (int n = blockIdx.x; n < Nn; n += gridDim.x) {
        float v = g_h1[(size_t)n * Cc + c];
        s += v; s2 += v * v;
    }
    atomicAdd(&g_bnsum[c], s);
    atomicAdd(&g_bnsum[Cc + c], s2);
}

__global__ void k_bn0_final(const float* __restrict__ g, const float* __restrict__ b) {
    int c = threadIdx.x;
    if (c < Cc) {
        float mean = g_bnsum[c] / (float)Nn;
        float var  = fmaxf(g_bnsum[Cc + c] / (float)Nn - mean * mean, 0.f);
        float sc = g[c] * rsqrtf(var + EPSB);
        g_sc0[c] = sc;
        g_sh0[c] = b[c] - mean * sc;
    }
}

// ---------------- normalize + pool ----------------
__global__ void k_pool(const int* __restrict__ batch) {
    int c = threadIdx.x;  // 128
    int per = (Nn + gridDim.x - 1) / gridDim.x;
    int s = blockIdx.x * per;
    int e = min(Nn, s + per);
    if (s >= e) return;
    float sc = g_sc0[c], sh = g_sh0[c];
    int cur = batch[s];
    float a = 0.f;
    for (int n = s; n < e; n++) {
        int gi = batch[n];
        if (gi != cur) { atomicAdd(&g_hp[cur * Cc + c], a); a = 0.f; cur = gi; }
        a += g_h1[(size_t)n * Cc + c] * sc + sh;
    }
    atomicAdd(&g_hp[cur * Cc + c], a);
}

// ---------------- FC stack ----------------
__global__ void k_fc1(const float* __restrict__ w, const float* __restrict__ b) {
    int idx = blockIdx.x * blockDim.x + threadIdx.x;
    if (idx >= Gg * 512) return;
    int c = idx & 511, r = idx >> 9;
    float s = b[c];
#pragma unroll 8
    for (int k = 0; k < Cc; k++) s += g_hp[r * Cc + k] * w[k * 512 + c];
    g_z1[idx] = s;
}

__global__ void k_bn1(const float* __restrict__ g, const float* __restrict__ b) {
    int c = blockIdx.x * blockDim.x + threadIdx.x;
    if (c >= 512) return;
    float s = 0.f, s2 = 0.f;
    for (int r = 0; r < Gg; r++) { float v = g_z1[r * 512 + c]; s += v; s2 += v * v; }
    float mean = s / (float)Gg;
    float var = fmaxf(s2 / (float)Gg - mean * mean, 0.f);
    float sc = g[c] * rsqrtf(var + EPSB);
    g_sc1[c] = sc; g_sh1[c] = b[c] - mean * sc;
}

__global__ void k_fc2(const float* __restrict__ w, const float* __restrict__ b) {
    int idx = blockIdx.x * blockDim.x + threadIdx.x;
    if (idx >= Gg * 256) return;
    int c = idx & 255, r = idx >> 8;
    float s = b[c];
#pragma unroll 8
    for (int k = 0; k < 512; k++) {
        float v = fmaxf(g_z1[r * 512 + k] * g_sc1[k] + g_sh1[k], 0.f);
        s += v * w[k * 256 + c];
    }
    g_z2[idx] = s;
}

__global__ void k_bn2(const float* __restrict__ g, const float* __restrict__ b) {
    int c = threadIdx.x;
    if (c >= 256) return;
    float s = 0.f, s2 = 0.f;
    for (int r = 0; r < Gg; r++) { float v = g_z2[r * 256 + c]; s += v; s2 += v * v; }
    float mean = s / (float)Gg;
    float var = fmaxf(s2 / (float)Gg - mean * mean, 0.f);
    float sc = g[c] * rsqrtf(var + EPSB);
    g_sc2[c] = sc; g_sh2[c] = b[c] - mean * sc;
}

__global__ void k_fc3(const float* __restrict__ w, const float* __restrict__ b,
                      const float* __restrict__ g3, const float* __restrict__ b3,
                      float* __restrict__ out) {
    __shared__ float red[256];
    __shared__ float z3[64];
    __shared__ float mv[2];
    int t = threadIdx.x;
    int r = t >> 2, p = t & 3;
    float s = 0.f;
    for (int k = p * 64; k < p * 64 + 64; k++) {
        float v = fmaxf(g_z2[r * 256 + k] * g_sc2[k] + g_sh2[k], 0.f);
        s += v * w[k];
    }
    red[t] = s;
    __syncthreads();
    if (p == 0) z3[r] = red[t] + red[t + 1] + red[t + 2] + red[t + 3] + b[0];
    __syncthreads();
    if (t == 0) {
        float m = 0.f;
        for (int i = 0; i < 64; i++) m += z3[i];
        m /= 64.f;
        float v = 0.f;
        for (int i = 0; i < 64; i++) { float d = z3[i] - m; v += d * d; }
        v /= 64.f;
        mv[0] = m; mv[1] = rsqrtf(v + EPSB);
    }
    __syncthreads();
    if (t < 64) out[t] = (z3[t] - mv[0]) * mv[1] * g3[0] + b3[0];
}

// ---------------- launch ----------------
extern "C" void kernel_launch(void* const* d_in, const int* in_sizes, int n_in,
                              void* d_out, int out_size) {
    const float* x        = (const float*)d_in[0];
    const float* gat_w    = (const float*)d_in[1];
    const float* gat_asrc = (const float*)d_in[2];
    const float* gat_adst = (const float*)d_in[3];
    const float* gat_bias = (const float*)d_in[4];
    const float* mlp_w    = (const float*)d_in[5];
    const float* mlp_b    = (const float*)d_in[6];
    const float* bn0_g    = (const float*)d_in[7];
    const float* bn0_b    = (const float*)d_in[8];
    const float* fc1_w    = (const float*)d_in[9];
    const float* fc1_b    = (const float*)d_in[10];
    const float* bn1_g    = (const float*)d_in[11];
    const float* bn1_b    = (const float*)d_in[12];
    const float* fc2_w    = (const float*)d_in[13];
    const float* fc2_b    = (const float*)d_in[14];
    const float* bn2_g    = (const float*)d_in[15];
    const float* bn2_b    = (const float*)d_in[16];
    const float* fc3_w    = (const float*)d_in[17];
    const float* fc3_b    = (const float*)d_in[18];
    const float* bn3_g    = (const float*)d_in[19];
    const float* bn3_b    = (const float*)d_in[20];
    const int*   ei       = (const int*)d_in[21];
    const int*   batch    = (const int*)d_in[22];
    float* out = (float*)d_out;

    // order chosen so gemm0 is the 4th launch (ncu lands there)
    k_init<<<(Nn + 255) / 256, 256>>>();
    k_degree<<<(ET + 255) / 256, 256>>>(ei);
    k_scan<<<1, 1024>>>();
    k_gemm<0><<<dim3((Nn + 127) / 128, HC / 128), 256>>>(
        x, gat_w, nullptr, nullptr, gat_asrc, gat_adst, Nn, 448, HC);
    k_edge<<<(ET + 255) / 256, 256>>>(ei);
    k_agg<<<Nn, 256>>>();
    k_gemm<1><<<dim3((Nn + 127) / 128, Cc / 128), 256>>>(
        nullptr, mlp_w, mlp_b, gat_bias, nullptr, nullptr, Nn, HC, Cc);
    k_bn0_stats<<<512, 128>>>();
    k_bn0_final<<<1, 128>>>(bn0_g, bn0_b);
    k_pool<<<200, 128>>>(batch);
    k_fc1<<<(Gg * 512 + 255) / 256, 256>>>(fc1_w, fc1_b);
    k_bn1<<<2, 256>>>(bn1_g, bn1_b);
    k_fc2<<<(Gg * 256 + 255) / 256, 256>>>(fc2_w, fc2_b);
    k_bn2<<<1, 256>>>(bn2_g, bn2_b);
    k_fc3<<<1, 256>>>(fc3_w, fc3_b, bn3_g, bn3_b, out);
}

// round 8
// speedup vs baseline: 1.2743x; 1.0206x over previous
#include <cuda_runtime.h>
#include <math.h>

#define Nn 30000
#define Ee 960000
#define ET (Ee + Nn)
#define Hh 2
#define Cc 128
#define HC 256
#define Gg 64
#define EPSB 1e-5f

typedef unsigned long long ull;

// ---------------- scratch (device globals; no allocation allowed) ----------------
__device__ float  g_xp[(size_t)Nn * HC];     // x @ gat_w          [N,256]
__device__ float  g_as[Nn * Hh];             // attention src dots [N,2]
__device__ float  g_ad[Nn * Hh];             // attention dst dots [N,2]
__device__ int    g_deg[Nn];                 // in-degree
__device__ int    g_ptr[Nn + 1];             // CSR offsets
__device__ int    g_cur[Nn];                 // scatter cursors
__device__ int4   g_csre[ET];                // CSR edge: {src, w0, w1, pad}
__device__ float  g_acc[(size_t)Nn * HC];    // normalized aggregation
__device__ float  g_h1[(size_t)Nn * Cc];     // elu(out) @ mlp_w + b
__device__ float  g_bnsum[2 * Cc];
__device__ float  g_sc0[Cc], g_sh0[Cc];
__device__ float  g_hp[Gg * Cc];
__device__ float  g_z1[Gg * 512];
__device__ float  g_sc1[512], g_sh1[512];
__device__ float  g_z2[Gg * 256];
__device__ float  g_sc2[256], g_sh2[256];

// ---------------- f32x2 helpers ----------------
__device__ __forceinline__ ull pk2(float lo, float hi) {
    ull d;
    asm("mov.b64 %0, {%1, %2};" : "=l"(d) : "r"(__float_as_uint(lo)), "r"(__float_as_uint(hi)));
    return d;
}
__device__ __forceinline__ float2 upk(ull v) {
    unsigned lo, hi;
    asm("mov.b64 {%0, %1}, %2;" : "=r"(lo), "=r"(hi) : "l"(v));
    return make_float2(__uint_as_float(lo), __uint_as_float(hi));
}
__device__ __forceinline__ ull fma2(ull a, ull b, ull c) {
    ull d;
    asm("fma.rn.f32x2 %0, %1, %2, %3;" : "=l"(d) : "l"(a), "l"(b), "l"(c));
    return d;
}

// ---------------- init ----------------
__global__ void k_init() {
    int i = blockIdx.x * blockDim.x + threadIdx.x;
    if (i < Nn)      g_deg[i] = 0;
    if (i < Gg * Cc) g_hp[i] = 0.f;
    if (i < 2 * Cc)  g_bnsum[i] = 0.f;
}

// ---------------- f32x2 GEMM: 128x128x32, 256 thr, 8x8/thread, 2 CTAs/SM --------
// K-step 32 per sync (halves barrier count, doubles LDG batching); single buffer.
// MODE 0: C(g_xp) = Aext @ B;  epilogue also writes attention dots g_as/g_ad
// MODE 1: C(g_h1) = elu(g_acc + abias) @ B + cbias
template <int MODE>
__global__ void __launch_bounds__(256, 2)
k_gemm(const float* __restrict__ Aext, const float* __restrict__ B,
       const float* __restrict__ cbias, const float* __restrict__ abias,
       const float* __restrict__ asrc, const float* __restrict__ adst,
       int M, int K, int Nc) {
    __shared__ float As[32][128];
    __shared__ float Bs[32][128];
    int t = threadIdx.x;
    int tx = t & 15, ty = t >> 4;
    int m0 = blockIdx.x * 128, n0 = blockIdx.y * 128;
    int ar_ = t >> 1, akc = (t & 1) * 16;       // A: 4 float4 per thread
    int bkb = t >> 4, bc4 = (t & 15) * 8;       // B: rows bkb, bkb+16; 2 float4 each
    int steps = K >> 5;
    bool rowok = (m0 + ar_) < M;
    const float* Ab = ((MODE == 0) ? Aext : (const float*)g_acc) + (size_t)(m0 + ar_) * K + akc;
    const float* Bb = B + (size_t)bkb * Nc + n0 + bc4;

    ull acc[4][8];
#pragma unroll
    for (int i = 0; i < 4; i++)
#pragma unroll
        for (int j = 0; j < 8; j++) acc[i][j] = 0ull;

    for (int it = 0; it < steps; it++) {
        int k0 = it << 5;
        float4 va[4];
        float4 vb[4];
#pragma unroll
        for (int q = 0; q < 4; q++) va[q] = make_float4(0.f, 0.f, 0.f, 0.f);
        if (rowok) {
#pragma unroll
            for (int q = 0; q < 4; q++) va[q] = *(const float4*)(Ab + k0 + q * 4);
            if (MODE == 1) {
                int gk = k0 + akc;
#pragma unroll
                for (int q = 0; q < 4; q++) {
                    float f[4] = {va[q].x, va[q].y, va[q].z, va[q].w};
#pragma unroll
                    for (int j = 0; j < 4; j++) {
                        float u = f[j] + __ldg(abias + gk + q * 4 + j);
                        f[j] = u > 0.f ? u : (__expf(u) - 1.f);
                    }
                    va[q] = make_float4(f[0], f[1], f[2], f[3]);
                }
            }
        }
        vb[0] = *(const float4*)(Bb + (size_t)k0 * Nc);
        vb[1] = *(const float4*)(Bb + (size_t)k0 * Nc + 4);
        vb[2] = *(const float4*)(Bb + (size_t)(k0 + 16) * Nc);
        vb[3] = *(const float4*)(Bb + (size_t)(k0 + 16) * Nc + 4);

        __syncthreads();   // previous compute done before overwrite
#pragma unroll
        for (int q = 0; q < 4; q++) {
            As[akc + q * 4 + 0][ar_] = va[q].x;
            As[akc + q * 4 + 1][ar_] = va[q].y;
            As[akc + q * 4 + 2][ar_] = va[q].z;
            As[akc + q * 4 + 3][ar_] = va[q].w;
        }
        *(float4*)&Bs[bkb][bc4]          = vb[0];
        *(float4*)&Bs[bkb][bc4 + 4]      = vb[1];
        *(float4*)&Bs[bkb + 16][bc4]     = vb[2];
        *(float4*)&Bs[bkb + 16][bc4 + 4] = vb[3];
        __syncthreads();

#pragma unroll
        for (int k = 0; k < 32; k++) {
            float4 x0 = *(const float4*)&As[k][ty * 8];
            float4 x1 = *(const float4*)&As[k][ty * 8 + 4];
            float4 y0 = *(const float4*)&Bs[k][tx * 8];
            float4 y1 = *(const float4*)&Bs[k][tx * 8 + 4];
            ull A2[4] = {pk2(x0.x, x0.y), pk2(x0.z, x0.w),
                         pk2(x1.x, x1.y), pk2(x1.z, x1.w)};
            float bb[8] = {y0.x, y0.y, y0.z, y0.w, y1.x, y1.y, y1.z, y1.w};
#pragma unroll
            for (int j = 0; j < 8; j++) {
                ull B2 = pk2(bb[j], bb[j]);
#pragma unroll
                for (int i = 0; i < 4; i++) acc[i][j] = fma2(A2[i], B2, acc[i][j]);
            }
        }
    }

    float* Cp = (MODE == 0) ? g_xp : g_h1;
    float cb[8];
#pragma unroll
    for (int j = 0; j < 8; j++) cb[j] = cbias ? cbias[n0 + tx * 8 + j] : 0.f;

    float sa[8], da[8];
    int h = n0 >> 7;
    if (MODE == 0) {
#pragma unroll
        for (int j = 0; j < 8; j++) {
            sa[j] = asrc[(h << 7) + tx * 8 + j];
            da[j] = adst[(h << 7) + tx * 8 + j];
        }
    }

#pragma unroll
    for (int i = 0; i < 4; i++) {
        float2 p[8];
#pragma unroll
        for (int j = 0; j < 8; j++) p[j] = upk(acc[i][j]);
        int re = m0 + ty * 8 + i * 2;
        int gc = n0 + tx * 8;
        if (re < M) {
            *(float4*)(Cp + (size_t)re * Nc + gc) =
                make_float4(p[0].x + cb[0], p[1].x + cb[1], p[2].x + cb[2], p[3].x + cb[3]);
            *(float4*)(Cp + (size_t)re * Nc + gc + 4) =
                make_float4(p[4].x + cb[4], p[5].x + cb[5], p[6].x + cb[6], p[7].x + cb[7]);
        }
        if (re + 1 < M) {
            *(float4*)(Cp + (size_t)(re + 1) * Nc + gc) =
                make_float4(p[0].y + cb[0], p[1].y + cb[1], p[2].y + cb[2], p[3].y + cb[3]);
            *(float4*)(Cp + (size_t)(re + 1) * Nc + gc + 4) =
                make_float4(p[4].y + cb[4], p[5].y + cb[5], p[6].y + cb[6], p[7].y + cb[7]);
        }
        if (MODE == 0) {
            float s0 = 0.f, d0 = 0.f, s1 = 0.f, d1 = 0.f;
#pragma unroll
            for (int j = 0; j < 8; j++) {
                s0 += p[j].x * sa[j]; d0 += p[j].x * da[j];
                s1 += p[j].y * sa[j]; d1 += p[j].y * da[j];
            }
#pragma unroll
            for (int msk = 1; msk < 16; msk <<= 1) {
                s0 += __shfl_xor_sync(0xFFFFFFFFu, s0, msk);
                d0 += __shfl_xor_sync(0xFFFFFFFFu, d0, msk);
                s1 += __shfl_xor_sync(0xFFFFFFFFu, s1, msk);
                d1 += __shfl_xor_sync(0xFFFFFFFFu, d1, msk);
            }
            if (tx == 0) {
                if (re < M)     { g_as[re * 2 + h] = s0;       g_ad[re * 2 + h] = d0; }
                if (re + 1 < M) { g_as[(re + 1) * 2 + h] = s1; g_ad[(re + 1) * 2 + h] = d1; }
            }
        }
    }
}

// ---------------- degree count ----------------
__global__ void k_degree(const int* __restrict__ ei) {
    int i = blockIdx.x * blockDim.x + threadIdx.x;
    if (i >= ET) return;
    int dst = (i < Ee) ? ei[Ee + i] : (i - Ee);
    atomicAdd(&g_deg[dst], 1);
}

// ---------------- exclusive scan (single block) ----------------
__global__ void k_scan() {
    __shared__ int sh[1024];
    int t = threadIdx.x;
    int s = t * 30, e = min(Nn, s + 30);
    int sum = 0;
    for (int i = s; i < e; i++) sum += g_deg[i];
    sh[t] = sum;
    __syncthreads();
    for (int off = 1; off < 1024; off <<= 1) {
        int v = (t >= off) ? sh[t - off] : 0;
        __syncthreads();
        sh[t] += v;
        __syncthreads();
    }
    int run = t ? sh[t - 1] : 0;
    for (int i = s; i < e; i++) {
        g_ptr[i] = run;
        g_cur[i] = run;
        run += g_deg[i];
    }
    if (t == 1023) g_ptr[Nn] = sh[1023];
}

// ---------------- fused edge: logit -> exp -> CSR scatter (packed 16B) ----------
__global__ void k_edge(const int* __restrict__ ei) {
    int i = blockIdx.x * blockDim.x + threadIdx.x;
    if (i >= ET) return;
    int src, dst;
    if (i < Ee) { src = ei[i]; dst = ei[Ee + i]; }
    else        { src = dst = i - Ee; }
    float2 as = *(const float2*)(g_as + src * 2);
    float2 ad = *(const float2*)(g_ad + dst * 2);
    float l0 = as.x + ad.x; l0 = l0 > 0.f ? l0 : 0.2f * l0;
    float l1 = as.y + ad.y; l1 = l1 > 0.f ? l1 : 0.2f * l1;
    float w0 = __expf(l0), w1 = __expf(l1);
    int pos = atomicAdd(&g_cur[dst], 1);
    g_csre[pos] = make_int4(src, __float_as_int(w0), __float_as_int(w1), 0);
}

// ---------------- aggregation: block per dst, smem-staged records, 2-edge ILP ----
__global__ void __launch_bounds__(256) k_agg() {
    __shared__ int4   se[128];
    __shared__ float4 sha[256];
    __shared__ float  shw[256];
    int dst = blockIdx.x;
    int t = threadIdx.x;
    int grp = t >> 6, l = t & 63;
    int beg = g_ptr[dst], end = g_ptr[dst + 1];
    int deg = end - beg;
    bool hi = l >= 32;
    float4 acc0 = make_float4(0.f, 0.f, 0.f, 0.f);
    float4 acc1 = make_float4(0.f, 0.f, 0.f, 0.f);
    float wsum = 0.f;

    for (int base = 0; base < deg; base += 128) {
        int cnt = min(128, deg - base);
        if (t < cnt) se[t] = g_csre[beg + base + t];   // coalesced, once per chunk
        __syncthreads();
        int e = grp;
        for (; e + 4 < cnt; e += 8) {                  // 2 edges in flight per group
            int4 e0 = se[e], e1 = se[e + 4];
            float w0 = hi ? __int_as_float(e0.z) : __int_as_float(e0.y);
            float w1 = hi ? __int_as_float(e1.z) : __int_as_float(e1.y);
            float4 v0 = __ldg((const float4*)(g_xp + (size_t)e0.x * HC) + l);
            float4 v1 = __ldg((const float4*)(g_xp + (size_t)e1.x * HC) + l);
            acc0.x += v0.x * w0; acc0.y += v0.y * w0;
            acc0.z += v0.z * w0; acc0.w += v0.w * w0;
            acc1.x += v1.x * w1; acc1.y += v1.y * w1;
            acc1.z += v1.z * w1; acc1.w += v1.w * w1;
            wsum += w0 + w1;
        }
        if (e < cnt) {
            int4 e0 = se[e];
            float w0 = hi ? __int_as_float(e0.z) : __int_as_float(e0.y);
            float4 v0 = __ldg((const float4*)(g_xp + (size_t)e0.x * HC) + l);
            acc0.x += v0.x * w0; acc0.y += v0.y * w0;
            acc0.z += v0.z * w0; acc0.w += v0.w * w0;
            wsum += w0;
        }
        __syncthreads();
    }
    acc0.x += acc1.x; acc0.y += acc1.y; acc0.z += acc1.z; acc0.w += acc1.w;
    sha[t] = acc0; shw[t] = wsum;
    __syncthreads();
    if (grp == 0) {
        float4 a = sha[t], b = sha[t + 64], c = sha[t + 128], d = sha[t + 192];
        float rd = 1.f / (shw[t] + shw[t + 64] + shw[t + 128] + shw[t + 192]);
        float4 r = make_float4((a.x + b.x + c.x + d.x) * rd,
                               (a.y + b.y + c.y + d.y) * rd,
                               (a.z + b.z + c.z + d.z) * rd,
                               (a.w + b.w + c.w + d.w) * rd);
        *((float4*)(g_acc + (size_t)dst * HC) + l) = r;
    }
}

// ---------------- BN0 stats ----------------
__global__ void k_bn0_stats() {
    int c = threadIdx.x;  // 128
    float s = 0.f, s2 = 0.f;
    for (int n = blockIdx.x; n < Nn; n += gridDim.x) {
        float v = g_h1[(size_t)n * Cc + c];
        s += v; s2 += v * v;
    }
    atomicAdd(&g_bnsum[c], s);
    atomicAdd(&g_bnsum[Cc + c], s2);
}

__global__ void k_bn0_final(const float* __restrict__ g, const float* __restrict__ b) {
    int c = threadIdx.x;
    if (c < Cc) {
        float mean = g_bnsum[c] / (float)Nn;
        float var  = fmaxf(g_bnsum[Cc + c] / (float)Nn - mean * mean, 0.f);
        float sc = g[c] * rsqrtf(var + EPSB);
        g_sc0[c] = sc;
        g_sh0[c] = b[c] - mean * sc;
    }
}

// ---------------- normalize + pool ----------------
__global__ void k_pool(const int* __restrict__ batch) {
    int c = threadIdx.x;  // 128
    int per = (Nn + gridDim.x - 1) / gridDim.x;
    int s = blockIdx.x * per;
    int e = min(Nn, s + per);
    if (s >= e) return;
    float sc = g_sc0[c], sh = g_sh0[c];
    int cur = batch[s];
    float a = 0.f;
    for (int n = s; n < e; n++) {
        int gi = batch[n];
        if (gi != cur) { atomicAdd(&g_hp[cur * Cc + c], a); a = 0.f; cur = gi; }
        a += g_h1[(size_t)n * Cc + c] * sc + sh;
    }
    atomicAdd(&g_hp[cur * Cc + c], a);
}

// ---------------- FC stack ----------------
__global__ void k_fc1(const float* __restrict__ w, const float* __restrict__ b) {
    int idx = blockIdx.x * blockDim.x + threadIdx.x;
    if (idx >= Gg * 512) return;
    int c = idx & 511, r = idx >> 9;
    float s = b[c];
#pragma unroll 8
    for (int k = 0; k < Cc; k++) s += g_hp[r * Cc + k] * w[k * 512 + c];
    g_z1[idx] = s;
}

__global__ void k_bn1(const float* __restrict__ g, const float* __restrict__ b) {
    int c = blockIdx.x * blockDim.x + threadIdx.x;
    if (c >= 512) return;
    float s = 0.f, s2 = 0.f;
    for (int r = 0; r < Gg; r++) { float v = g_z1[r * 512 + c]; s += v; s2 += v * v; }
    float mean = s / (float)Gg;
    float var = fmaxf(s2 / (float)Gg - mean * mean, 0.f);
    float sc = g[c] * rsqrtf(var + EPSB);
    g_sc1[c] = sc; g_sh1[c] = b[c] - mean * sc;
}

__global__ void k_fc2(const float* __restrict__ w, const float* __restrict__ b) {
    int idx = blockIdx.x * blockDim.x + threadIdx.x;
    if (idx >= Gg * 256) return;
    int c = idx & 255, r = idx >> 8;
    float s = b[c];
#pragma unroll 8
    for (int k = 0; k < 512; k++) {
        float v = fmaxf(g_z1[r * 512 + k] * g_sc1[k] + g_sh1[k], 0.f);
        s += v * w[k * 256 + c];
    }
    g_z2[idx] = s;
}

__global__ void k_bn2(const float* __restrict__ g, const float* __restrict__ b) {
    int c = threadIdx.x;
    if (c >= 256) return;
    float s = 0.f, s2 = 0.f;
    for (int r = 0; r < Gg; r++) { float v = g_z2[r * 256 + c]; s += v; s2 += v * v; }
    float mean = s / (float)Gg;
    float var = fmaxf(s2 / (float)Gg - mean * mean, 0.f);
    float sc = g[c] * rsqrtf(var + EPSB);
    g_sc2[c] = sc; g_sh2[c] = b[c] - mean * sc;
}

__global__ void k_fc3(const float* __restrict__ w, const float* __restrict__ b,
                      const float* __restrict__ g3, const float* __restrict__ b3,
                      float* __restrict__ out) {
    __shared__ float red[256];
    __shared__ float z3[64];
    __shared__ float mv[2];
    int t = threadIdx.x;
    int r = t >> 2, p = t & 3;
    float s = 0.f;
    for (int k = p * 64; k < p * 64 + 64; k++) {
        float v = fmaxf(g_z2[r * 256 + k] * g_sc2[k] + g_sh2[k], 0.f);
        s += v * w[k];
    }
    red[t] = s;
    __syncthreads();
    if (p == 0) z3[r] = red[t] + red[t + 1] + red[t + 2] + red[t + 3] + b[0];
    __syncthreads();
    if (t == 0) {
        float m = 0.f;
        for (int i = 0; i < 64; i++) m += z3[i];
        m /= 64.f;
        float v = 0.f;
        for (int i = 0; i < 64; i++) { float d = z3[i] - m; v += d * d; }
        v /= 64.f;
        mv[0] = m; mv[1] = rsqrtf(v + EPSB);
    }
    __syncthreads();
    if (t < 64) out[t] = (z3[t] - mv[0]) * mv[1] * g3[0] + b3[0];
}

// ---------------- launch ----------------
extern "C" void kernel_launch(void* const* d_in, const int* in_sizes, int n_in,
                              void* d_out, int out_size) {
    const float* x        = (const float*)d_in[0];
    const float* gat_w    = (const float*)d_in[1];
    const float* gat_asrc = (const float*)d_in[2];
    const float* gat_adst = (const float*)d_in[3];
    const float* gat_bias = (const float*)d_in[4];
    const float* mlp_w    = (const float*)d_in[5];
    const float* mlp_b    = (const float*)d_in[6];
    const float* bn0_g    = (const float*)d_in[7];
    const float* bn0_b    = (const float*)d_in[8];
    const float* fc1_w    = (const float*)d_in[9];
    const float* fc1_b    = (const float*)d_in[10];
    const float* bn1_g    = (const float*)d_in[11];
    const float* bn1_b    = (const float*)d_in[12];
    const float* fc2_w    = (const float*)d_in[13];
    const float* fc2_b    = (const float*)d_in[14];
    const float* bn2_g    = (const float*)d_in[15];
    const float* bn2_b    = (const float*)d_in[16];
    const float* fc3_w    = (const float*)d_in[17];
    const float* fc3_b    = (const float*)d_in[18];
    const float* bn3_g    = (const float*)d_in[19];
    const float* bn3_b    = (const float*)d_in[20];
    const int*   ei       = (const int*)d_in[21];
    const int*   batch    = (const int*)d_in[22];
    float* out = (float*)d_out;

    // order chosen so gemm0 is the 4th launch (ncu lands there)
    k_init<<<(Nn + 255) / 256, 256>>>();
    k_degree<<<(ET + 255) / 256, 256>>>(ei);
    k_scan<<<1, 1024>>>();
    k_gemm<0><<<dim3((Nn + 127) / 128, HC / 128), 256>>>(
        x, gat_w, nullptr, nullptr, gat_asrc, gat_adst, Nn, 448, HC);
    k_edge<<<(ET + 255) / 256, 256>>>(ei);
    k_agg<<<Nn, 256>>>();
    k_gemm<1><<<dim3((Nn + 127) / 128, Cc / 128), 256>>>(
        nullptr, mlp_w, mlp_b, gat_bias, nullptr, nullptr, Nn, HC, Cc);
    k_bn0_stats<<<512, 128>>>();
    k_bn0_final<<<1, 128>>>(bn0_g, bn0_b);
    k_pool<<<200, 128>>>(batch);
    k_fc1<<<(Gg * 512 + 255) / 256, 256>>>(fc1_w, fc1_b);
    k_bn1<<<2, 256>>>(bn1_g, bn1_b);
    k_fc2<<<(Gg * 256 + 255) / 256, 256>>>(fc2_w, fc2_b);
    k_bn2<<<1, 256>>>(bn2_g, bn2_b);
    k_fc3<<<1, 256>>>(fc3_w, fc3_b, bn3_g, bn3_b, out);
}